// round 1
// baseline (speedup 1.0000x reference)
#include <cuda_runtime.h>

#define N_NODES 768
#define F_DIM   64
#define DE_DIM  32
#define H_DIM   64
#define H2_DIM  128

// Scratch (allocation-free rule: __device__ globals)
__device__ float g_P [N_NODES * H_DIM];
__device__ float g_Q [N_NODES * H_DIM];
__device__ float g_X1[N_NODES * H_DIM];
__device__ float g_X2[N_NODES * H_DIM];

// P[i,h] = x_i @ (W[0:64] - W[64:128]) + ba ;  Q[j,h] = x_j @ W[64:128]
// so pre-activation of layer-a for edge (i,j) = P[i] + Q[j] + e_ij @ W[128:160]
__global__ void pq_kernel(const float* __restrict__ x,
                          const float* __restrict__ W,
                          const float* __restrict__ ba,
                          float* __restrict__ P,
                          float* __restrict__ Q)
{
    __shared__ float sx[F_DIM];
    int i = blockIdx.x, h = threadIdx.x;
    sx[h] = x[i * F_DIM + h];
    __syncthreads();
    float p = ba[h], q = 0.f;
#pragma unroll
    for (int f = 0; f < F_DIM; f++) {
        float xv = sx[f];
        float wi = W[f * H_DIM + h];
        float wd = W[(F_DIM + f) * H_DIM + h];
        p = fmaf(xv, wi - wd, p);
        q = fmaf(xv, wd, q);
    }
    P[i * H_DIM + h] = p;
    Q[i * H_DIM + h] = q;
}

// One block per row i. Compact active j's, then each warp handles one edge:
//   z = relu(P_i + Q_j + e_ij @ We)      (We = W rows [128:160])
//   m = relu(z @ Wb + bb)
//   acc_i += m
__global__ __launch_bounds__(256) void edge_kernel(
    const float* __restrict__ A,  const float* __restrict__ e,
    const float* __restrict__ P,  const float* __restrict__ Q,
    const float* __restrict__ W,  const float* __restrict__ Wb,
    const float* __restrict__ bb, float* __restrict__ out)
{
    __shared__ float sWe[DE_DIM * H_DIM];   // 8 KB
    __shared__ float sWb[H_DIM * H_DIM];    // 16 KB
    __shared__ float sbb[H_DIM];
    __shared__ float sP[H_DIM];
    __shared__ float red[8][H_DIM];         // per-warp partial accumulators
    __shared__ unsigned short slist[N_NODES];
    __shared__ int scnt;

    const int i    = blockIdx.x;
    const int tid  = threadIdx.x;
    const int warp = tid >> 5;
    const int lane = tid & 31;
    const unsigned FULL = 0xffffffffu;

    if (tid == 0) scnt = 0;
    for (int k = tid; k < DE_DIM * H_DIM; k += 256)
        sWe[k] = W[(2 * F_DIM) * H_DIM + k];
    for (int k = tid; k < H_DIM * H_DIM; k += 256)
        sWb[k] = Wb[k];
    if (tid < H_DIM) { sbb[tid] = bb[tid]; sP[tid] = P[i * H_DIM + tid]; }
    __syncthreads();

    // compact adjacency row (order irrelevant: sum is commutative)
    for (int j = tid; j < N_NODES; j += 256)
        if (A[i * N_NODES + j] != 0.0f) {
            int pos = atomicAdd(&scnt, 1);
            slist[pos] = (unsigned short)j;
        }
    __syncthreads();
    const int cnt = scnt;

    const int h0 = lane, h1 = lane + 32;
    float r0 = 0.f, r1 = 0.f;

    for (int eidx = warp; eidx < cnt; eidx += 8) {
        const int j = slist[eidx];

        float a0 = sP[h0] + Q[j * H_DIM + h0];
        float a1 = sP[h1] + Q[j * H_DIM + h1];

        // e row: lane l loads e[i,j,l]  (DE=32 == warp width)
        float ev = e[(i * N_NODES + j) * DE_DIM + lane];
#pragma unroll
        for (int de = 0; de < DE_DIM; de++) {
            float evb = __shfl_sync(FULL, ev, de);
            a0 = fmaf(evb, sWe[de * H_DIM + h0], a0);
            a1 = fmaf(evb, sWe[de * H_DIM + h1], a1);
        }
        float z0 = fmaxf(a0, 0.f);
        float z1 = fmaxf(a1, 0.f);

        // m = relu(z @ Wb + bb) — z distributed 2/lane, broadcast via shfl
        float m0 = sbb[h0], m1 = sbb[h1];
#pragma unroll
        for (int k = 0; k < 32; k++) {
            float zk = __shfl_sync(FULL, z0, k);
            m0 = fmaf(zk, sWb[k * H_DIM + h0], m0);
            m1 = fmaf(zk, sWb[k * H_DIM + h1], m1);
        }
#pragma unroll
        for (int k = 0; k < 32; k++) {
            float zk = __shfl_sync(FULL, z1, k);
            m0 = fmaf(zk, sWb[(k + 32) * H_DIM + h0], m0);
            m1 = fmaf(zk, sWb[(k + 32) * H_DIM + h1], m1);
        }
        r0 += fmaxf(m0, 0.f);
        r1 += fmaxf(m1, 0.f);
    }

    red[warp][h0] = r0;
    red[warp][h1] = r1;
    __syncthreads();
    if (tid < H_DIM) {
        float s = 0.f;
#pragma unroll
        for (int w = 0; w < 8; w++) s += red[w][tid];
        out[i * H_DIM + tid] = s;
    }
}

// out[i] = sigmoid( relu(x2_i @ W3 + b3) @ W4 + b4 )
__global__ __launch_bounds__(128) void final_kernel(
    const float* __restrict__ x,
    const float* __restrict__ W3, const float* __restrict__ b3,
    const float* __restrict__ W4, const float* __restrict__ b4,
    float* __restrict__ out)
{
    __shared__ float sx[H_DIM];
    __shared__ float sred[H2_DIM];
    const int i = blockIdx.x, t = threadIdx.x;
    if (t < H_DIM) sx[t] = x[i * H_DIM + t];
    __syncthreads();

    float h = b3[t];
#pragma unroll
    for (int k = 0; k < H_DIM; k++)
        h = fmaf(sx[k], W3[k * H2_DIM + t], h);
    h = fmaxf(h, 0.f);

    sred[t] = h * W4[t];
    __syncthreads();
#pragma unroll
    for (int s = 64; s > 0; s >>= 1) {
        if (t < s) sred[t] += sred[t + s];
        __syncthreads();
    }
    if (t == 0) {
        float v = sred[0] + b4[0];
        out[i] = 1.0f / (1.0f + expf(-v));
    }
}

extern "C" void kernel_launch(void* const* d_in, const int* in_sizes, int n_in,
                              void* d_out, int out_size)
{
    const float* A   = (const float*)d_in[0];
    const float* x   = (const float*)d_in[1];
    const float* e   = (const float*)d_in[2];
    const float* W1a = (const float*)d_in[3];
    const float* b1a = (const float*)d_in[4];
    const float* W1b = (const float*)d_in[5];
    const float* b1b = (const float*)d_in[6];
    const float* W2a = (const float*)d_in[7];
    const float* b2a = (const float*)d_in[8];
    const float* W2b = (const float*)d_in[9];
    const float* b2b = (const float*)d_in[10];
    const float* W3  = (const float*)d_in[11];
    const float* b3  = (const float*)d_in[12];
    const float* W4  = (const float*)d_in[13];
    const float* b4  = (const float*)d_in[14];
    float* out = (float*)d_out;

    float *P, *Q, *X1, *X2;
    cudaGetSymbolAddress((void**)&P,  g_P);
    cudaGetSymbolAddress((void**)&Q,  g_Q);
    cudaGetSymbolAddress((void**)&X1, g_X1);
    cudaGetSymbolAddress((void**)&X2, g_X2);

    // Layer 1
    pq_kernel<<<N_NODES, H_DIM>>>(x, W1a, b1a, P, Q);
    edge_kernel<<<N_NODES, 256>>>(A, e, P, Q, W1a, W1b, b1b, X1);
    // Layer 2
    pq_kernel<<<N_NODES, H_DIM>>>(X1, W2a, b2a, P, Q);
    edge_kernel<<<N_NODES, 256>>>(A, e, P, Q, W2a, W2b, b2b, X2);
    // Head
    final_kernel<<<N_NODES, H2_DIM>>>(X2, W3, b3, W4, b4, out);
}

// round 2
// speedup vs baseline: 1.0082x; 1.0082x over previous
#include <cuda_runtime.h>

#define NN 768
#define FD 64
#define DE 32
#define HD 64
#define H2 128

// Scratch (allocation-free rule: __device__ globals), 16B-aligned for float4 ops
__device__ __align__(16) float g_P [NN * HD];
__device__ __align__(16) float g_Q [NN * HD];
__device__ __align__(16) float g_X1[NN * HD];
__device__ __align__(16) float g_X2[NN * HD];
__device__ unsigned g_cnt;
__device__ unsigned g_edges[NN * NN];

// P[i,h] = x_i @ (W[0:64]-W[64:128]) + ba ;  Q[j,h] = x_j @ W[64:128]
__global__ void pq_kernel(const float* __restrict__ x,
                          const float* __restrict__ W,
                          const float* __restrict__ ba,
                          float* __restrict__ P,
                          float* __restrict__ Q)
{
    __shared__ float sx[FD];
    int i = blockIdx.x, h = threadIdx.x;
    sx[h] = x[i * FD + h];
    __syncthreads();
    float p = ba[h], q = 0.f;
#pragma unroll
    for (int f = 0; f < FD; f++) {
        float xv = sx[f];
        float wi = W[f * HD + h];
        float wd = W[(FD + f) * HD + h];
        p = fmaf(xv, wi - wd, p);
        q = fmaf(xv, wd, q);
    }
    P[i * HD + h] = p;
    Q[i * HD + h] = q;
}

// Build global edge list: pk = (i<<10)|j  for A[i,j] != 0
__global__ void compact_kernel(const float* __restrict__ A)
{
    __shared__ unsigned lcnt, lbase;
    const int i = blockIdx.x, tid = threadIdx.x;
    if (tid == 0) lcnt = 0;
    __syncthreads();
    unsigned myj[3]; int mc = 0;
    for (int j = tid; j < NN; j += 256)
        if (A[i * NN + j] != 0.0f) myj[mc++] = (unsigned)j;
    unsigned lpos = mc ? atomicAdd(&lcnt, (unsigned)mc) : 0u;
    __syncthreads();
    if (tid == 0) lbase = atomicAdd(&g_cnt, lcnt);
    __syncthreads();
    unsigned b = lbase + lpos;
    for (int t = 0; t < mc; t++)
        g_edges[b + t] = ((unsigned)i << 10) | myj[t];
}

// Lane-per-edge: each lane computes one edge's full MLP in registers.
// Weight reads are warp-uniform broadcast LDS.128; no shuffles at all.
// smem (floats): sWe 2048 | sWb 4096 | sbb 64 | zs 64*128 | esh 32*128
__global__ __launch_bounds__(128) void edge_kernel(
    const float* __restrict__ e,  const float* __restrict__ P,
    const float* __restrict__ Q,  const float* __restrict__ W,
    const float* __restrict__ Wb, const float* __restrict__ bb,
    float* __restrict__ out)
{
    extern __shared__ float sm[];
    float* sWe = sm;             // 2048
    float* sWb = sm + 2048;      // 4096
    float* sbb = sm + 6144;      // 64
    float* zs  = sm + 6208;      // 8192  [k][tid]
    float* esh = sm + 14400;     // 4096  [de][tid]

    const int tid  = threadIdx.x;
    const int lane = tid & 31;
    const int warp = tid >> 5;

    for (int k = tid; k < DE * HD; k += 128) sWe[k] = W[(2 * FD) * HD + k];
    for (int k = tid; k < HD * HD; k += 128) sWb[k] = Wb[k];
    if (tid < HD) sbb[tid] = bb[tid];
    __syncthreads();

    const unsigned cnt   = g_cnt;
    const unsigned gw    = blockIdx.x * 4u + (unsigned)warp;
    const unsigned nwarp = gridDim.x * 4u;

    for (unsigned base = gw * 32u; base < cnt; base += nwarp * 32u) {
        const unsigned eid = base + (unsigned)lane;
        const bool valid = (eid < cnt);
        const unsigned pk = g_edges[valid ? eid : 0u];
        const int i = (int)(pk >> 10);
        const int j = (int)(pk & 1023u);

        // a[h] = P[i,h] + Q[j,h]
        float a[HD];
        {
            const float4* Pp = (const float4*)(P + i * HD);
            const float4* Qp = (const float4*)(Q + j * HD);
#pragma unroll
            for (int h4 = 0; h4 < 16; h4++) {
                float4 p = Pp[h4], q = Qp[h4];
                a[h4 * 4 + 0] = p.x + q.x;
                a[h4 * 4 + 1] = p.y + q.y;
                a[h4 * 4 + 2] = p.z + q.z;
                a[h4 * 4 + 3] = p.w + q.w;
            }
        }

        // stage this lane's e-row into its private smem column
        {
            const float4* ep = (const float4*)(e + ((size_t)((unsigned)i * NN + (unsigned)j)) * DE);
#pragma unroll
            for (int q4 = 0; q4 < 8; q4++) {
                float4 v = ep[q4];
                esh[(q4 * 4 + 0) * 128 + tid] = v.x;
                esh[(q4 * 4 + 1) * 128 + tid] = v.y;
                esh[(q4 * 4 + 2) * 128 + tid] = v.z;
                esh[(q4 * 4 + 3) * 128 + tid] = v.w;
            }
        }

        // layer a: a += e @ We   (We broadcast from smem)
#pragma unroll 2
        for (int de = 0; de < DE; de++) {
            const float ev = esh[de * 128 + tid];
            const float4* wr = (const float4*)(sWe + de * HD);
#pragma unroll
            for (int h4 = 0; h4 < 16; h4++) {
                float4 w = wr[h4];
                a[h4 * 4 + 0] = fmaf(ev, w.x, a[h4 * 4 + 0]);
                a[h4 * 4 + 1] = fmaf(ev, w.y, a[h4 * 4 + 1]);
                a[h4 * 4 + 2] = fmaf(ev, w.z, a[h4 * 4 + 2]);
                a[h4 * 4 + 3] = fmaf(ev, w.w, a[h4 * 4 + 3]);
            }
        }

        // z = relu(a), parked in private smem column (dynamic-k reads)
#pragma unroll
        for (int h = 0; h < HD; h++) zs[h * 128 + tid] = fmaxf(a[h], 0.f);

        // layer b: m = z @ Wb + bb
        float m[HD];
        {
            const float4* bp = (const float4*)sbb;
#pragma unroll
            for (int h4 = 0; h4 < 16; h4++) {
                float4 b4 = bp[h4];
                m[h4 * 4 + 0] = b4.x; m[h4 * 4 + 1] = b4.y;
                m[h4 * 4 + 2] = b4.z; m[h4 * 4 + 3] = b4.w;
            }
        }
#pragma unroll 2
        for (int k = 0; k < HD; k++) {
            const float zk = zs[k * 128 + tid];
            const float4* wr = (const float4*)(sWb + k * HD);
#pragma unroll
            for (int h4 = 0; h4 < 16; h4++) {
                float4 w = wr[h4];
                m[h4 * 4 + 0] = fmaf(zk, w.x, m[h4 * 4 + 0]);
                m[h4 * 4 + 1] = fmaf(zk, w.y, m[h4 * 4 + 1]);
                m[h4 * 4 + 2] = fmaf(zk, w.z, m[h4 * 4 + 2]);
                m[h4 * 4 + 3] = fmaf(zk, w.w, m[h4 * 4 + 3]);
            }
        }

        // relu + scatter-accumulate into out[i,:]
        if (valid) {
            float4* op = (float4*)(out + i * HD);
#pragma unroll
            for (int h4 = 0; h4 < 16; h4++) {
                float4 v = make_float4(fmaxf(m[h4 * 4 + 0], 0.f),
                                       fmaxf(m[h4 * 4 + 1], 0.f),
                                       fmaxf(m[h4 * 4 + 2], 0.f),
                                       fmaxf(m[h4 * 4 + 3], 0.f));
                atomicAdd(op + h4, v);
            }
        }
    }
}

// out[i] = sigmoid( relu(x2_i @ W3 + b3) @ W4 + b4 )
__global__ __launch_bounds__(128) void final_kernel(
    const float* __restrict__ x,
    const float* __restrict__ W3, const float* __restrict__ b3,
    const float* __restrict__ W4, const float* __restrict__ b4,
    float* __restrict__ out)
{
    __shared__ float sx[HD];
    __shared__ float sred[H2];
    const int i = blockIdx.x, t = threadIdx.x;
    if (t < HD) sx[t] = x[i * HD + t];
    __syncthreads();

    float h = b3[t];
#pragma unroll
    for (int k = 0; k < HD; k++)
        h = fmaf(sx[k], W3[k * H2 + t], h);
    h = fmaxf(h, 0.f);

    sred[t] = h * W4[t];
    __syncthreads();
#pragma unroll
    for (int s = 64; s > 0; s >>= 1) {
        if (t < s) sred[t] += sred[t + s];
        __syncthreads();
    }
    if (t == 0) {
        float v = sred[0] + b4[0];
        out[i] = 1.0f / (1.0f + expf(-v));
    }
}

extern "C" void kernel_launch(void* const* d_in, const int* in_sizes, int n_in,
                              void* d_out, int out_size)
{
    const float* A   = (const float*)d_in[0];
    const float* x   = (const float*)d_in[1];
    const float* e   = (const float*)d_in[2];
    const float* W1a = (const float*)d_in[3];
    const float* b1a = (const float*)d_in[4];
    const float* W1b = (const float*)d_in[5];
    const float* b1b = (const float*)d_in[6];
    const float* W2a = (const float*)d_in[7];
    const float* b2a = (const float*)d_in[8];
    const float* W2b = (const float*)d_in[9];
    const float* b2b = (const float*)d_in[10];
    const float* W3  = (const float*)d_in[11];
    const float* b3  = (const float*)d_in[12];
    const float* W4  = (const float*)d_in[13];
    const float* b4  = (const float*)d_in[14];
    float* out = (float*)d_out;

    float *P, *Q, *X1, *X2; unsigned* cntp;
    cudaGetSymbolAddress((void**)&P,  g_P);
    cudaGetSymbolAddress((void**)&Q,  g_Q);
    cudaGetSymbolAddress((void**)&X1, g_X1);
    cudaGetSymbolAddress((void**)&X2, g_X2);
    cudaGetSymbolAddress((void**)&cntp, g_cnt);

    const int SMEM = (2048 + 4096 + 64 + 64 * 128 + 32 * 128) * 4;  // 73984 B
    cudaFuncSetAttribute(edge_kernel, cudaFuncAttributeMaxDynamicSharedMemorySize, SMEM);

    // reset scratch
    cudaMemsetAsync(cntp, 0, sizeof(unsigned));
    cudaMemsetAsync(X1, 0, NN * HD * sizeof(float));
    cudaMemsetAsync(X2, 0, NN * HD * sizeof(float));

    compact_kernel<<<NN, 256>>>(A);

    // Layer 1
    pq_kernel<<<NN, HD>>>(x, W1a, b1a, P, Q);
    edge_kernel<<<232, 128, SMEM>>>(e, P, Q, W1a, W1b, b1b, X1);
    // Layer 2
    pq_kernel<<<NN, HD>>>(X1, W2a, b2a, P, Q);
    edge_kernel<<<232, 128, SMEM>>>(e, P, Q, W2a, W2b, b2b, X2);
    // Head
    final_kernel<<<NN, H2>>>(X2, W3, b3, W4, b4, out);
}

// round 3
// speedup vs baseline: 1.6617x; 1.6482x over previous
#include <cuda_runtime.h>

#define NN 768
#define FD 64
#define DE 32
#define HD 64
#define H2 128
#define EGRID 148

// Scratch (allocation-free rule: __device__ globals), 16B-aligned
__device__ __align__(16) float g_P [NN * HD];
__device__ __align__(16) float g_Q [NN * HD];
__device__ __align__(16) float g_X1[NN * HD];
__device__ __align__(16) float g_X2[NN * HD];
__device__ unsigned g_cnt;
__device__ unsigned g_edges[NN * NN];

// P[i,h] = x_i @ (W[0:64]-W[64:128]) + ba ;  Q[j,h] = x_j @ W[64:128]
// Also zeroes the next layer's accumulator buffer (Xz).
__global__ __launch_bounds__(256) void pq_kernel(
    const float* __restrict__ x, const float* __restrict__ W,
    const float* __restrict__ ba, float* __restrict__ P,
    float* __restrict__ Q, float* __restrict__ Xz)
{
    __shared__ float sx[4][FD];
    const int tid = threadIdx.x;
    const int nl  = tid >> 6;          // node within block (0..3)
    const int h   = tid & 63;
    const int node = blockIdx.x * 4 + nl;

    // zero accumulator slice: 12288 float4 total over 192*256 threads
    {
        unsigned g = blockIdx.x * 256u + (unsigned)tid;
        if (g < (NN * HD) / 4) ((float4*)Xz)[g] = make_float4(0.f, 0.f, 0.f, 0.f);
    }

    sx[nl][h] = x[node * FD + h];
    __syncthreads();

    float p = ba[h], q = 0.f;
#pragma unroll
    for (int f = 0; f < FD; f++) {
        float xv = sx[nl][f];
        float wi = W[f * HD + h];
        float wd = W[(FD + f) * HD + h];
        p = fmaf(xv, wi - wd, p);
        q = fmaf(xv, wd, q);
    }
    P[node * HD + h] = p;
    Q[node * HD + h] = q;
}

// Build global edge list: pk = (i<<10)|j for A[i,j] != 0 (row-clustered order)
__global__ void compact_kernel(const float* __restrict__ A)
{
    __shared__ unsigned lcnt, lbase;
    const int i = blockIdx.x, tid = threadIdx.x;
    if (tid == 0) lcnt = 0;
    __syncthreads();
    unsigned myj[3]; int mc = 0;
    for (int j = tid; j < NN; j += 256)
        if (A[i * NN + j] != 0.0f) myj[mc++] = (unsigned)j;
    unsigned lpos = mc ? atomicAdd(&lcnt, (unsigned)mc) : 0u;
    __syncthreads();
    if (tid == 0) lbase = atomicAdd(&g_cnt, lcnt);
    __syncthreads();
    unsigned b = lbase + lpos;
    for (int t = 0; t < mc; t++)
        g_edges[b + t] = ((unsigned)i << 10) | myj[t];
}

// Lane-per-edge, all per-lane state in registers; smem = weights only.
__global__ __launch_bounds__(256) void edge_kernel(
    const float* __restrict__ e,  const float* __restrict__ P,
    const float* __restrict__ Q,  const float* __restrict__ W,
    const float* __restrict__ Wb, const float* __restrict__ bb,
    float* __restrict__ out)
{
    __shared__ float sWe[DE * HD];   // 8 KB
    __shared__ float sWb[HD * HD];   // 16 KB
    __shared__ float sbb[HD];

    const int tid  = threadIdx.x;
    const int lane = tid & 31;
    const int warp = tid >> 5;

    for (int k = tid; k < DE * HD; k += 256) sWe[k] = W[(2 * FD) * HD + k];
    for (int k = tid; k < HD * HD; k += 256) sWb[k] = Wb[k];
    if (tid < HD) sbb[tid] = bb[tid];
    __syncthreads();

    const unsigned cnt  = g_cnt;
    const unsigned nbat = (cnt + 31u) >> 5;
    // interleaved mapping: every SM gets an equal share of batches
    const unsigned slot   = (unsigned)warp * EGRID + blockIdx.x;
    const unsigned stride = EGRID * 8u;

    for (unsigned bat = slot; bat < nbat; bat += stride) {
        const unsigned eid = bat * 32u + (unsigned)lane;
        const bool valid = (eid < cnt);
        const unsigned pk = g_edges[valid ? eid : (cnt - 1u)];
        const int i = (int)(pk >> 10);
        const int j = (int)(pk & 1023u);

        // e-row into registers (constant-index unrolled use below)
        float ev[DE];
        {
            const float4* ep = (const float4*)(e + ((size_t)(i * NN + j)) * DE);
#pragma unroll
            for (int q4 = 0; q4 < 8; q4++) {
                float4 v = ep[q4];
                ev[q4 * 4 + 0] = v.x; ev[q4 * 4 + 1] = v.y;
                ev[q4 * 4 + 2] = v.z; ev[q4 * 4 + 3] = v.w;
            }
        }

        // z = relu(P_i + Q_j + e @ We)
        float z[HD];
        {
            const float4* Pp = (const float4*)(P + i * HD);
            const float4* Qp = (const float4*)(Q + j * HD);
#pragma unroll
            for (int h4 = 0; h4 < 16; h4++) {
                float4 p = Pp[h4], q = Qp[h4];
                z[h4 * 4 + 0] = p.x + q.x;
                z[h4 * 4 + 1] = p.y + q.y;
                z[h4 * 4 + 2] = p.z + q.z;
                z[h4 * 4 + 3] = p.w + q.w;
            }
        }
#pragma unroll
        for (int de = 0; de < DE; de++) {
            const float evv = ev[de];
            const float4* wr = (const float4*)(sWe + de * HD);
#pragma unroll
            for (int h4 = 0; h4 < 16; h4++) {
                float4 w = wr[h4];
                z[h4 * 4 + 0] = fmaf(evv, w.x, z[h4 * 4 + 0]);
                z[h4 * 4 + 1] = fmaf(evv, w.y, z[h4 * 4 + 1]);
                z[h4 * 4 + 2] = fmaf(evv, w.z, z[h4 * 4 + 2]);
                z[h4 * 4 + 3] = fmaf(evv, w.w, z[h4 * 4 + 3]);
            }
        }
#pragma unroll
        for (int h = 0; h < HD; h++) z[h] = fmaxf(z[h], 0.f);

        // m = relu(z @ Wb + bb), computed in two 32-wide halves (reg pressure)
        float4* op = (float4*)(out + i * HD);
#pragma unroll
        for (int half = 0; half < 2; half++) {
            float m[32];
            {
                const float4* bp = (const float4*)(sbb + half * 32);
#pragma unroll
                for (int c = 0; c < 8; c++) {
                    float4 b4 = bp[c];
                    m[c * 4 + 0] = b4.x; m[c * 4 + 1] = b4.y;
                    m[c * 4 + 2] = b4.z; m[c * 4 + 3] = b4.w;
                }
            }
#pragma unroll
            for (int k = 0; k < HD; k++) {
                const float zk = z[k];
                const float4* wr = (const float4*)(sWb + k * HD + half * 32);
#pragma unroll
                for (int c = 0; c < 8; c++) {
                    float4 w = wr[c];
                    m[c * 4 + 0] = fmaf(zk, w.x, m[c * 4 + 0]);
                    m[c * 4 + 1] = fmaf(zk, w.y, m[c * 4 + 1]);
                    m[c * 4 + 2] = fmaf(zk, w.z, m[c * 4 + 2]);
                    m[c * 4 + 3] = fmaf(zk, w.w, m[c * 4 + 3]);
                }
            }
            if (valid) {
#pragma unroll
                for (int c = 0; c < 8; c++) {
                    float4 v = make_float4(fmaxf(m[c * 4 + 0], 0.f),
                                           fmaxf(m[c * 4 + 1], 0.f),
                                           fmaxf(m[c * 4 + 2], 0.f),
                                           fmaxf(m[c * 4 + 3], 0.f));
                    atomicAdd(op + half * 8 + c, v);
                }
            }
        }
    }
}

// out[i] = sigmoid( relu(x2_i @ W3 + b3) @ W4 + b4 )
__global__ __launch_bounds__(128) void final_kernel(
    const float* __restrict__ x,
    const float* __restrict__ W3, const float* __restrict__ b3,
    const float* __restrict__ W4, const float* __restrict__ b4,
    float* __restrict__ out)
{
    __shared__ float sx[HD];
    __shared__ float sred[H2];
    const int i = blockIdx.x, t = threadIdx.x;
    if (t < HD) sx[t] = x[i * HD + t];
    __syncthreads();

    float h = b3[t];
#pragma unroll
    for (int k = 0; k < HD; k++)
        h = fmaf(sx[k], W3[k * H2 + t], h);
    h = fmaxf(h, 0.f);

    sred[t] = h * W4[t];
    __syncthreads();
#pragma unroll
    for (int s = 64; s > 0; s >>= 1) {
        if (t < s) sred[t] += sred[t + s];
        __syncthreads();
    }
    if (t == 0) {
        float v = sred[0] + b4[0];
        out[i] = 1.0f / (1.0f + expf(-v));
    }
}

extern "C" void kernel_launch(void* const* d_in, const int* in_sizes, int n_in,
                              void* d_out, int out_size)
{
    const float* A   = (const float*)d_in[0];
    const float* x   = (const float*)d_in[1];
    const float* e   = (const float*)d_in[2];
    const float* W1a = (const float*)d_in[3];
    const float* b1a = (const float*)d_in[4];
    const float* W1b = (const float*)d_in[5];
    const float* b1b = (const float*)d_in[6];
    const float* W2a = (const float*)d_in[7];
    const float* b2a = (const float*)d_in[8];
    const float* W2b = (const float*)d_in[9];
    const float* b2b = (const float*)d_in[10];
    const float* W3  = (const float*)d_in[11];
    const float* b3  = (const float*)d_in[12];
    const float* W4  = (const float*)d_in[13];
    const float* b4  = (const float*)d_in[14];
    float* out = (float*)d_out;

    float *P, *Q, *X1, *X2; unsigned* cntp;
    cudaGetSymbolAddress((void**)&P,  g_P);
    cudaGetSymbolAddress((void**)&Q,  g_Q);
    cudaGetSymbolAddress((void**)&X1, g_X1);
    cudaGetSymbolAddress((void**)&X2, g_X2);
    cudaGetSymbolAddress((void**)&cntp, g_cnt);

    cudaMemsetAsync(cntp, 0, sizeof(unsigned));
    compact_kernel<<<NN, 256>>>(A);

    // Layer 1 (pq also zeroes X1)
    pq_kernel<<<NN / 4, 256>>>(x, W1a, b1a, P, Q, X1);
    edge_kernel<<<EGRID, 256>>>(e, P, Q, W1a, W1b, b1b, X1);
    // Layer 2 (pq also zeroes X2)
    pq_kernel<<<NN / 4, 256>>>(X1, W2a, b2a, P, Q, X2);
    edge_kernel<<<EGRID, 256>>>(e, P, Q, W2a, W2b, b2b, X2);
    // Head
    final_kernel<<<NN, H2>>>(X2, W3, b3, W4, b4, out);
}